// round 10
// baseline (speedup 1.0000x reference)
#include <cuda_runtime.h>
#include <cuda_bf16.h>
#include <cstdint>

#define FULL_MASK 0xFFFFFFFFu
#define TAGS 32
#define START 30
#define STOP 31
#define RING 6

__device__ float g_partial[2048];
__device__ int   g_count = 0;

typedef unsigned long long ull;

// ---- packed fp32x2 helpers (Blackwell FFMA2 path, full fp32 precision) ----
__device__ __forceinline__ ull pack2(float lo, float hi) {
    ull r; asm("mov.b64 %0, {%1, %2};" : "=l"(r) : "f"(lo), "f"(hi)); return r;
}
__device__ __forceinline__ void unpack2(float& lo, float& hi, ull v) {
    asm("mov.b64 {%0, %1}, %2;" : "=f"(lo), "=f"(hi) : "l"(v));
}
__device__ __forceinline__ ull fma2(ull a, ull b, ull c) {
    ull r; asm("fma.rn.f32x2 %0, %1, %2, %3;" : "=l"(r) : "l"(a), "l"(b), "l"(c)); return r;
}
__device__ __forceinline__ ull mul2(ull a, ull b) {
    ull r; asm("mul.rn.f32x2 %0, %1, %2;" : "=l"(r) : "l"(a), "l"(b)); return r;
}
__device__ __forceinline__ ull add2(ull a, ull b) {
    ull r; asm("add.rn.f32x2 %0, %1, %2;" : "=l"(r) : "l"(a), "l"(b)); return r;
}
// volatile (no blanket memory clobber): ordered w.r.t. the volatile STS below,
// but FMAs and LDGs may be scheduled freely around them.
__device__ __forceinline__ void lds_v2u64(ull& a, ull& b, uint32_t addr) {
    asm volatile("ld.shared.v2.u64 {%0, %1}, [%2];"
                 : "=l"(a), "=l"(b) : "r"(addr));
}
__device__ __forceinline__ void sts32(uint32_t addr, float v) {
    asm volatile("st.shared.b32 [%0], %1;" :: "r"(addr), "f"(v));
}

// dual packed matvec: two independent 32-dots, loads interleaved so both
// chains' FMAs overlap. Returns (sumA, sumB).
__device__ __forceinline__ float2 matvec_dual(uint32_t baseA, uint32_t baseB,
                                              const ull* EA, const ull* EB) {
    ull cA[8], cB[8];
#pragma unroll
    for (int k = 0; k < 8; ++k) {
        ull qa, qb;
        lds_v2u64(qa, qb, baseA + 16 * k);
        cA[k] = fma2(qb, EA[2 * k + 1], mul2(qa, EA[2 * k]));
        lds_v2u64(qa, qb, baseB + 16 * k);
        cB[k] = fma2(qb, EB[2 * k + 1], mul2(qa, EB[2 * k]));
    }
    ull gA = add2(add2(add2(cA[0], cA[1]), add2(cA[2], cA[3])),
                  add2(add2(cA[4], cA[5]), add2(cA[6], cA[7])));
    ull gB = add2(add2(add2(cB[0], cB[1]), add2(cB[2], cB[3])),
                  add2(add2(cB[4], cB[5]), add2(cB[6], cB[7])));
    float la, ha, lb, hb;
    unpack2(la, ha, gA);
    unpack2(lb, hb, gB);
    return make_float2(la + ha, lb + hb);
}

// One block = one WARP = one batch. The warp runs the forward recursion
// (to split point m) and the backward recursion (down to m) as two
// interleaved, independent dependency chains -> 2x ILP per warp, perfectly
// length-balanced because both halves belong to the same sequence.
// Z = sum_i alphaExp_m(i) * betaExp_m(i).
__global__ void __launch_bounds__(32, 8)
crf_nll_kernel(const float* __restrict__ feats,
               const float* __restrict__ trans,
               const int*   __restrict__ tags,
               const int*   __restrict__ lens,
               float* __restrict__ out,
               int B, int L)
{
    __shared__ __align__(16) float bufA[2][TAGS];
    __shared__ __align__(16) float bufB[2][TAGS];

    int b    = blockIdx.x;
    int lane = threadIdx.x;

    const float* fb = feats + (size_t)b * L * TAGS;
    const int*   tb = tags  + (size_t)b * L;
    int len    = lens[b];
    int m      = (len - 1) >> 1;       // forward steps: t = 1..m
    int stepsB = (len - 1) - m;        // backward steps: m or m+1

    // E packed both ways:
    //   EA[2k],EA[2k+1]: column lane of E  (forward:  p_new[j] = sum_i p[i] E[i][j])
    //   EB[2k],EB[2k+1]: row    lane of E  (backward: q_new[i] = sum_j E[i][j] r[j])
    ull EA[TAGS / 2], EB[TAGS / 2];
#pragma unroll
    for (int k = 0; k < TAGS / 2; ++k) {
        EA[k] = pack2(__expf(trans[(2 * k) * TAGS + lane]),
                      __expf(trans[(2 * k + 1) * TAGS + lane]));
        EB[k] = pack2(__expf(trans[lane * TAGS + 2 * k]),
                      __expf(trans[lane * TAGS + 2 * k + 1]));
    }

    // forward init: alpha0 -> exp-domain
    float a0 = trans[START * TAGS + lane] + fb[lane];
    float mx = a0;
#pragma unroll
    for (int o = 16; o; o >>= 1) mx = fmaxf(mx, __shfl_xor_sync(FULL_MASK, mx, o));
    float p   = __expf(a0 - mx);
    float lsA = mx;

    // backward init: beta_{len-1}(i) = trans[i][STOP]
    float qv  = __expf(trans[lane * TAGS + STOP]);
    float lsB = 0.f;

    // prefetch rings (clamped in-bounds; dead slots never consumed)
    float qF[RING], qB[RING];
#pragma unroll
    for (int k = 0; k < RING; ++k) {
        qF[k] = fb[min(1 + k, m) * TAGS + lane];
        qB[k] = fb[max(len - 1 - k, 0) * TAGS + lane];
    }

    uint32_t sbA = (uint32_t)__cvta_generic_to_shared(&bufA[0][0]);
    uint32_t sbB = (uint32_t)__cvta_generic_to_shared(&bufB[0][0]);

    // pipelined renorm state (both chains)
    float m0A = 1.f, rrA = 1.f, lgA = 0.f;
    float m0B = 1.f, rrB = 1.f, lgB = 0.f;

#pragma unroll 4
    for (int t = 1; t <= m; ++t) {
        float fA = __expf(qF[0]);
        float fB = __expf(qB[0]);
#pragma unroll
        for (int k = 0; k < RING - 1; ++k) { qF[k] = qF[k + 1]; qB[k] = qB[k + 1]; }
        qF[RING - 1] = fb[min(t + RING, m) * TAGS + lane];
        qB[RING - 1] = fb[max(len - 1 - RING - t, 0) * TAGS + lane];

        float r = qv * fB;              // backward pre-multiply
        int slot = t & 1;
        sts32(sbA + slot * (TAGS * 4) + lane * 4, p);
        sts32(sbB + slot * (TAGS * 4) + lane * 4, r);
        float2 s = matvec_dual(sbA + slot * (TAGS * 4), sbB + slot * (TAGS * 4), EA, EB);
        p  = s.x * fA;
        qv = s.y;

        int ph = t & 3;
        if (ph == 0) {
            m0A = __shfl_sync(FULL_MASK, p, 0);
            m0B = __shfl_sync(FULL_MASK, qv, 0);
        } else if (ph == 1) {
            rrA = __fdividef(1.0f, m0A);  lgA = __logf(m0A);
            rrB = __fdividef(1.0f, m0B);  lgB = __logf(m0B);
        } else if (ph == 3) {
            p  *= rrA;  lsA += lgA;       // only on-chain ops
            qv *= rrB;  lsB += lgB;
        }
    }

    // one leftover backward step when (len-1) is odd
    if (stepsB > m) {
        float fB = __expf(qB[0]);
        float r = qv * fB;
        int slot = (m + 1) & 1;
        sts32(sbB + slot * (TAGS * 4) + lane * 4, r);
        ull cB[8];
#pragma unroll
        for (int k = 0; k < 8; ++k) {
            ull qa, qb;
            lds_v2u64(qa, qb, sbB + slot * (TAGS * 4) + 16 * k);
            cB[k] = fma2(qb, EB[2 * k + 1], mul2(qa, EB[2 * k]));
        }
        ull gB = add2(add2(add2(cB[0], cB[1]), add2(cB[2], cB[3])),
                      add2(add2(cB[4], cB[5]), add2(cB[6], cB[7])));
        float lb, hb;
        unpack2(lb, hb, gB);
        qv = lb + hb;
    }

    // combine: Z = sum_i alphaExp_m(i) * betaExp_m(i)
    float v = p * qv;
#pragma unroll
    for (int o = 16; o; o >>= 1) v += __shfl_xor_sync(FULL_MASK, v, o);
    float fwd = lsA + lsB + __logf(v);

    // gold score (lane-strided gathers over the whole sequence)
    float midsum = 0.f;
    for (int t = lane; t < len - 1; t += 32) {
        int u = tb[t], w = tb[t + 1];
        midsum += trans[u * TAGS + w] + fb[(t + 1) * TAGS + w];
    }
#pragma unroll
    for (int o = 16; o; o >>= 1) midsum += __shfl_xor_sync(FULL_MASK, midsum, o);

    if (lane == 0) {
        int tag0 = tb[0];
        int tend = tb[len - 1];
        float gold = trans[START * TAGS + tag0] + fb[tag0]
                   + trans[tend * TAGS + STOP] + midsum;
        g_partial[b] = fwd - gold;
    }

    // fused deterministic final reduction (last block to finish)
    __threadfence();
    int old = 0;
    if (lane == 0) old = atomicAdd(&g_count, 1);
    old = __shfl_sync(FULL_MASK, old, 0);
    if (old == B - 1) {
        __threadfence();
        double acc = 0.0;
        for (int i = lane; i < B; i += 32)
            acc += (double)((volatile float*)g_partial)[i];
#pragma unroll
        for (int o = 16; o; o >>= 1)
            acc += __shfl_xor_sync(FULL_MASK, acc, o);
        if (lane == 0) {
            out[0] = (float)acc;
            g_count = 0;   // reset for next graph replay
        }
    }
}

extern "C" void kernel_launch(void* const* d_in, const int* in_sizes, int n_in,
                              void* d_out, int out_size)
{
    const float* feats = (const float*)d_in[0];
    const float* trans = (const float*)d_in[1];
    const int*   tags  = (const int*)d_in[2];
    const int*   lens  = (const int*)d_in[3];
    float* out = (float*)d_out;

    int B = in_sizes[3];                  // word_seq_lens: (B,)
    int L = in_sizes[2] / B;              // tags: (B, L)

    crf_nll_kernel<<<B, 32>>>(feats, trans, tags, lens, out, B, L);
}

// round 11
// speedup vs baseline: 1.0684x; 1.0684x over previous
#include <cuda_runtime.h>
#include <cuda_bf16.h>
#include <cstdint>

#define FULL_MASK 0xFFFFFFFFu
#define TAGS 32
#define START 30
#define STOP 31
#define RING 4

__device__ float g_partial[2048];
__device__ int   g_count = 0;

typedef unsigned long long ull;

__device__ __forceinline__ ull pack2(float lo, float hi) {
    ull r; asm("mov.b64 %0, {%1, %2};" : "=l"(r) : "f"(lo), "f"(hi)); return r;
}
__device__ __forceinline__ void unpack2(float& lo, float& hi, ull v) {
    asm("mov.b64 {%0, %1}, %2;" : "=f"(lo), "=f"(hi) : "l"(v));
}
__device__ __forceinline__ ull fma2(ull a, ull b, ull c) {
    ull r; asm("fma.rn.f32x2 %0, %1, %2, %3;" : "=l"(r) : "l"(a), "l"(b), "l"(c)); return r;
}
__device__ __forceinline__ ull mul2(ull a, ull b) {
    ull r; asm("mul.rn.f32x2 %0, %1, %2;" : "=l"(r) : "l"(a), "l"(b)); return r;
}
__device__ __forceinline__ ull add2(ull a, ull b) {
    ull r; asm("add.rn.f32x2 %0, %1, %2;" : "=l"(r) : "l"(a), "l"(b)); return r;
}
__device__ __forceinline__ void lds_v2u64(ull& a, ull& b, uint32_t addr) {
    asm volatile("ld.shared.v2.u64 {%0, %1}, [%2];" : "=l"(a), "=l"(b) : "r"(addr));
}
__device__ __forceinline__ void sts64(uint32_t addr, ull v) {
    asm volatile("st.shared.b64 [%0], %1;" :: "r"(addr), "l"(v));
}

// One warp = one batch. Lanes 0-15: forward chain (lane g owns output tags
// 2g,2g+1). Lanes 16-31: backward chain (owns rows 2g,2g+1). Per step each
// lane stores its 8B pair and loads its chain's 128B state: 2.25KB crossbar
// per warp-step (2 chain-steps) vs 4KB per chain-step in the broadcast layout.
// Each lane computes FULL dots for its 2 tags from register-resident E pairs.
__global__ void __launch_bounds__(32, 8)
crf_nll_kernel(const float* __restrict__ feats,
               const float* __restrict__ trans,
               const int*   __restrict__ tags,
               const int*   __restrict__ lens,
               float* __restrict__ out,
               int B, int L)
{
    __shared__ __align__(16) float buf[2][2][TAGS];   // slot, chain, tag
    __shared__ __align__(16) float qout[TAGS];

    int b    = blockIdx.x;
    int lane = threadIdx.x;
    bool isF = lane < 16;
    int g    = isF ? lane : lane - 16;
    int j0   = 2 * g;                      // owned tag/row pair

    const float* fb = feats + (size_t)b * L * TAGS;
    const int*   tb = tags  + (size_t)b * L;
    int len = lens[b];
    int m   = (len - 1) >> 1;              // fwd steps: 1..m
    int sB  = (len - 1) - m;               // bwd steps: 1..sB (sB >= m)
    int itmax = sB;

    // E pairs in registers: fwd lane needs columns j0,j0+1 over i-pairs;
    // bwd lane needs rows j0,j0+1 over j-pairs. Unified via base/stride.
    ull E0[16], E1[16];
    {
        int base0  = isF ? j0       : j0 * TAGS;
        int base1  = isF ? (j0 + 1) : (j0 + 1) * TAGS;
        int stride = isF ? TAGS : 1;
#pragma unroll
        for (int k = 0; k < 16; ++k) {
            E0[k] = pack2(__expf(trans[base0 + (2 * k) * stride]),
                          __expf(trans[base0 + (2 * k + 1) * stride]));
            E1[k] = pack2(__expf(trans[base1 + (2 * k) * stride]),
                          __expf(trans[base1 + (2 * k + 1) * stride]));
        }
    }

    // init: fwd pair = alpha0 components; bwd pair = trans[i][STOP].
    // Both shifted by their group max (exact bookkeeping via ls).
    float v0 = isF ? (trans[START * TAGS + j0]     + fb[j0])
                   : trans[j0 * TAGS + STOP];
    float v1 = isF ? (trans[START * TAGS + j0 + 1] + fb[j0 + 1])
                   : trans[(j0 + 1) * TAGS + STOP];
    float mx = fmaxf(v0, v1);
#pragma unroll
    for (int o = 8; o; o >>= 1) mx = fmaxf(mx, __shfl_xor_sync(FULL_MASK, mx, o));
    ull   p  = pack2(__expf(v0 - mx), __expf(v1 - mx));
    float ls = mx;

    // feat pair prefetch ring (float2 per lane, clamped in-bounds)
    float2 r[RING];
#pragma unroll
    for (int k = 0; k < RING; ++k) {
        int it = 1 + k;
        int idx = isF ? min(it, m) : max(len - it, 0);
        r[k] = *(const float2*)(fb + idx * TAGS + j0);
    }

    uint32_t sbase = (uint32_t)__cvta_generic_to_shared(&buf[0][0][0]);
    uint32_t choff = (isF ? 0u : (uint32_t)(TAGS * 4));

    float m0 = 1.f, rr = 1.f, lg = 0.f;

#pragma unroll 4
    for (int it = 1; it <= itmax; ++it) {
        float2 fq = r[0];
#pragma unroll
        for (int k = 0; k < RING - 1; ++k) r[k] = r[k + 1];
        {
            int nit = it + RING;
            int idx = isF ? min(nit, m) : max(len - nit, 0);
            r[RING - 1] = *(const float2*)(fb + idx * TAGS + j0);
        }
        float e0 = __expf(fq.x);
        float e1 = __expf(fq.y);
        ull ev = pack2(e0, e1);

        // bwd pre-multiplies its own components by exp(f); fwd stores raw p
        ull w = isF ? p : mul2(p, ev);

        int slot = it & 1;
        uint32_t base = sbase + (uint32_t)slot * (2 * TAGS * 4) + choff;
        sts64(base + j0 * 4, w);

        // full 32-term dots for both owned tags (4 accumulators)
        ull a00 = 0, a01 = 0, a10 = 0, a11 = 0;
#pragma unroll
        for (int k = 0; k < 8; ++k) {
            ull qa, qb;
            lds_v2u64(qa, qb, base + 16 * k);
            a00 = fma2(qa, E0[2 * k],     a00);
            a01 = fma2(qb, E0[2 * k + 1], a01);
            a10 = fma2(qa, E1[2 * k],     a10);
            a11 = fma2(qb, E1[2 * k + 1], a11);
        }
        float s0l, s0h, s1l, s1h;
        unpack2(s0l, s0h, add2(a00, a01));
        unpack2(s1l, s1h, add2(a10, a11));
        float s0 = s0l + s0h;
        float s1 = s1l + s1h;

        // fwd applies exp(f) post-dot; bwd already applied pre-store
        ull pn = isF ? pack2(s0 * e0, s1 * e1) : pack2(s0, s1);
        bool act = it <= (isF ? m : sB);
        p = act ? pn : p;

        // pipelined per-chain renorm (scale from chain-leader's first element)
        int ph = it & 3;
        if (ph == 0) {
            float px, py;
            unpack2(px, py, p);
            m0 = __shfl_sync(FULL_MASK, px, isF ? 0 : 16);
        } else if (ph == 1) {
            rr = __fdividef(1.0f, m0);
            lg = __logf(m0);
        } else if (ph == 3) {
            p = mul2(p, pack2(rr, rr));
            ls += lg;
        }
    }

    // combine: bwd publishes q; fwd computes Z = sum_i alpha[i]*beta[i]
    {
        float px, py;
        unpack2(px, py, p);
        if (!isF) { qout[j0] = px; qout[j0 + 1] = py; }
    }
    __syncwarp();
    float lsO = __shfl_sync(FULL_MASK, ls, 16);     // bwd logscale (read on lane 0)
    float px, py;
    unpack2(px, py, p);
    float v = px * qout[j0] + py * qout[j0 + 1];    // garbage on bwd lanes (unused)
#pragma unroll
    for (int o = 8; o; o >>= 1) v += __shfl_xor_sync(FULL_MASK, v, o);

    // gold score (lane-strided gathers, whole warp)
    float midsum = 0.f;
    for (int t = lane; t < len - 1; t += 32) {
        int u = tb[t], w = tb[t + 1];
        midsum += trans[u * TAGS + w] + fb[(t + 1) * TAGS + w];
    }
#pragma unroll
    for (int o = 16; o; o >>= 1) midsum += __shfl_xor_sync(FULL_MASK, midsum, o);

    if (lane == 0) {
        float fwd = ls + lsO + __logf(v);
        int tag0 = tb[0];
        int tend = tb[len - 1];
        float gold = trans[START * TAGS + tag0] + fb[tag0]
                   + trans[tend * TAGS + STOP] + midsum;
        g_partial[b] = fwd - gold;
    }

    // fused deterministic final reduction (last block to finish)
    __threadfence();
    int old = 0;
    if (lane == 0) old = atomicAdd(&g_count, 1);
    old = __shfl_sync(FULL_MASK, old, 0);
    if (old == B - 1) {
        __threadfence();
        double acc = 0.0;
        for (int i = lane; i < B; i += 32)
            acc += (double)((volatile float*)g_partial)[i];
#pragma unroll
        for (int o = 16; o; o >>= 1)
            acc += __shfl_xor_sync(FULL_MASK, acc, o);
        if (lane == 0) {
            out[0] = (float)acc;
            g_count = 0;   // reset for next graph replay
        }
    }
}

extern "C" void kernel_launch(void* const* d_in, const int* in_sizes, int n_in,
                              void* d_out, int out_size)
{
    const float* feats = (const float*)d_in[0];
    const float* trans = (const float*)d_in[1];
    const int*   tags  = (const int*)d_in[2];
    const int*   lens  = (const int*)d_in[3];
    float* out = (float*)d_out;

    int B = in_sizes[3];                  // word_seq_lens: (B,)
    int L = in_sizes[2] / B;              // tags: (B, L)

    crf_nll_kernel<<<B, 32>>>(feats, trans, tags, lens, out, B, L);
}